// round 1
// baseline (speedup 1.0000x reference)
#include <cuda_runtime.h>

#define NN   100000
#define DIM  64

// ---- scratch (allocation-free rule: __device__ globals) ----
__device__ float g_kyv[NN * DIM];   // K1 output ky_v; reused as K2 output v
__device__ float g_acc[NN * DIM];   // scatter accumulator
__device__ float g_cnt[NN];         // scatter counts (float for atomicAdd)

// ============================================================================
// Fused per-node kernel:  h = relu(ea@W1+b1);  W = h@W2+b2 (tile, in regs);
// y[n,c,j] = sum_k src[n,c*16+k] * W[n, c*256+k*16+j]   -> g_kyv
// K2 variant reads g_acc and scales output by 1/max(cnt,1).
// 32 nodes / block, 128 threads. Shared = 8 + 8 + 32 = 48 KB exactly.
// ============================================================================
template<int IS_K2>
__global__ __launch_bounds__(128, 4)
void fused_node_kernel(const float* __restrict__ xin,   // x (K1) / unused (K2)
                       const float* __restrict__ ea,
                       const float* __restrict__ W1,
                       const float* __restrict__ b1,
                       const float* __restrict__ W2,
                       const float* __restrict__ b2,
                       int n_nodes)
{
    __shared__ float sh_x [32 * 64];   // [node][feat]
    __shared__ float sh_ht[64 * 32];   // h transposed: [m][node]
    __shared__ float sh_w [32 * 256];  // W2 m-chunk [m_local][kj]; reused as Wt [node][kj]

    const int tid = threadIdx.x;
    const int nb  = blockIdx.x * 32;

    const float* src = IS_K2 ? g_acc : xin;

    // ---- stage x (32x64) ----
    #pragma unroll
    for (int i = 0; i < 16; i++) {
        int idx = tid + i * 128;            // n = idx>>6, f = idx&63
        int n = idx >> 6;
        sh_x[idx] = (nb + n < n_nodes) ? src[(size_t)nb * 64 + idx] : 0.0f;
    }
    // ---- compute h transposed: sh_ht[m*32+n] ----
    #pragma unroll
    for (int i = 0; i < 16; i++) {
        int idx = tid + i * 128;
        int m = idx >> 5, n = idx & 31;
        float hv = 0.0f;
        if (nb + n < n_nodes) {
            const float* e = ea + (size_t)(nb + n) * 3;
            hv = b1[m] + e[0] * W1[m] + e[1] * W1[64 + m] + e[2] * W1[128 + m];
            hv = fmaxf(hv, 0.0f);
        }
        sh_ht[m * 32 + n] = hv;
    }
    // ---- K1 also zeroes the scatter accumulators for its nodes ----
    if (!IS_K2) {
        #pragma unroll
        for (int i = 0; i < 16; i++) g_acc[(size_t)nb * 64 + tid + i * 128] = 0.0f;
        if (tid < 32) g_cnt[nb + tid] = 0.0f;
    }

    const int tgn = tid >> 5;        // warp id: node group (8 nodes)
    const int tkj = tid & 31;        // kj group: owns kj = tkj*8 .. tkj*8+7
    const int bn  = tid >> 2;        // phase-B node
    const int bj  = (tid & 3) * 4;   // phase-B j base

    float inv = 1.0f;
    if (IS_K2) inv = 1.0f / fmaxf(g_cnt[nb + bn], 1.0f);   // mean is linear: fold here

    __syncthreads();

    for (int c = 0; c < 4; c++) {
        // ---- Phase A: Wt[32 nodes][256 kj] = b2 + H(32x64) @ W2c(64x256) ----
        float acc[8][8];
        #pragma unroll
        for (int u = 0; u < 8; u++) {
            float bb = b2[c * 256 + tkj * 8 + u];
            #pragma unroll
            for (int ni = 0; ni < 8; ni++) acc[ni][u] = bb;
        }
        for (int mc = 0; mc < 2; mc++) {
            __syncthreads();   // protect sh_w reuse
            #pragma unroll
            for (int i = 0; i < 64; i++) {
                int idx = tid + i * 128;
                int r = idx >> 8, col = idx & 255;
                sh_w[idx] = W2[(size_t)(mc * 32 + r) * 1024 + c * 256 + col];
            }
            __syncthreads();
            #pragma unroll 8
            for (int mi = 0; mi < 32; mi++) {
                float4 h0 = *(const float4*)&sh_ht[(mc * 32 + mi) * 32 + tgn * 8];
                float4 h1 = *(const float4*)&sh_ht[(mc * 32 + mi) * 32 + tgn * 8 + 4];
                float4 w0 = *(const float4*)&sh_w[mi * 256 + tkj * 8];
                float4 w1 = *(const float4*)&sh_w[mi * 256 + tkj * 8 + 4];
                float hv[8] = {h0.x, h0.y, h0.z, h0.w, h1.x, h1.y, h1.z, h1.w};
                float wv[8] = {w0.x, w0.y, w0.z, w0.w, w1.x, w1.y, w1.z, w1.w};
                #pragma unroll
                for (int ni = 0; ni < 8; ni++)
                    #pragma unroll
                    for (int u = 0; u < 8; u++)
                        acc[ni][u] = fmaf(hv[ni], wv[u], acc[ni][u]);
            }
        }
        __syncthreads();
        #pragma unroll
        for (int ni = 0; ni < 8; ni++) {
            float4 a0 = make_float4(acc[ni][0], acc[ni][1], acc[ni][2], acc[ni][3]);
            float4 a1 = make_float4(acc[ni][4], acc[ni][5], acc[ni][6], acc[ni][7]);
            *(float4*)&sh_w[(tgn * 8 + ni) * 256 + tkj * 8]     = a0;
            *(float4*)&sh_w[(tgn * 8 + ni) * 256 + tkj * 8 + 4] = a1;
        }
        __syncthreads();
        // ---- Phase B: y[n,c,j] = sum_k x[n,c*16+k] * Wt[n][k*16+j] ----
        float yv[4] = {0.f, 0.f, 0.f, 0.f};
        #pragma unroll
        for (int k = 0; k < 16; k++) {
            float xv = sh_x[bn * 64 + c * 16 + k];
            #pragma unroll
            for (int jj = 0; jj < 4; jj++)
                yv[jj] = fmaf(xv, sh_w[bn * 256 + k * 16 + bj + jj], yv[jj]);
        }
        if (nb + bn < n_nodes) {
            #pragma unroll
            for (int jj = 0; jj < 4; jj++)
                g_kyv[(size_t)(nb + bn) * 64 + c * 16 + bj + jj] = yv[jj] * inv;
        }
    }
}

// ============================================================================
// Edge scatter: acc[dst] += ky_v[src], cnt[dst] += 1. 256 edges / block tile.
// Each warp: 2 edges per pass, 16 lanes/edge, float4 vector atomics.
// ============================================================================
__global__ __launch_bounds__(256)
void scatter_kernel(const int* __restrict__ ei, int n_edges)
{
    __shared__ int s_dst[256];
    __shared__ int s_src[256];
    const int tid  = threadIdx.x;
    const int base = blockIdx.x * 256;
    const int nE   = min(256, n_edges - base);
    if (nE <= 0) return;

    if (tid < nE) {
        s_dst[tid] = ei[base + tid];             // edge_index[0] = dst
        s_src[tid] = ei[n_edges + base + tid];   // edge_index[1] = src
    }
    __syncthreads();

    const int w    = tid >> 5;
    const int lane = tid & 31;
    const int half = lane >> 4;
    const int l16  = lane & 15;

    #pragma unroll 4
    for (int p = 0; p < 16; p++) {
        int le = w * 32 + p * 2 + half;
        if (le < nE) {
            int src = s_src[le];
            int dst = s_dst[le];
            float4 v = *(const float4*)&g_kyv[(size_t)src * 64 + l16 * 4];
            atomicAdd((float4*)&g_acc[(size_t)dst * 64 + l16 * 4], v);
            if (l16 == 0) atomicAdd(&g_cnt[dst], 1.0f);
        }
    }
}

// ============================================================================
// Mix: out[n,i] = mix_b[i] + sum_j v[n,j] * mix_W[i,j].  64 nodes / block.
// ============================================================================
__global__ __launch_bounds__(256)
void mix_kernel(const float* __restrict__ Wm, const float* __restrict__ bm,
                float* __restrict__ out, int n_nodes)
{
    __shared__ float s_w[64 * 65];   // transposed + padded: s_w[j*65+i]
    __shared__ float s_v[64 * 64];
    const int tid = threadIdx.x;
    const int nb  = blockIdx.x * 64;

    for (int idx = tid; idx < 4096; idx += 256) {
        int i2 = idx >> 6, j2 = idx & 63;
        s_w[j2 * 65 + i2] = Wm[idx];
    }
    for (int idx = tid; idx < 4096; idx += 256) {
        int n = idx >> 6;
        s_v[idx] = (nb + n < n_nodes) ? g_kyv[(size_t)nb * 64 + idx] : 0.0f;
    }
    __syncthreads();

    const int i  = tid & 63;
    const int ng = tid >> 6;           // 4 groups x 16 nodes
    const float bmi = bm[i];
    for (int r = 0; r < 16; r++) {
        int n = ng * 16 + r;
        if (nb + n >= n_nodes) break;
        float a = bmi;
        #pragma unroll
        for (int j = 0; j < 64; j++)
            a = fmaf(s_v[n * 64 + j], s_w[j * 65 + i], a);
        out[(size_t)(nb + n) * 64 + i] = a;
    }
}

// ============================================================================
extern "C" void kernel_launch(void* const* d_in, const int* in_sizes, int n_in,
                              void* d_out, int out_size)
{
    const float* x    = (const float*)d_in[0];
    const float* ea   = (const float*)d_in[1];
    const int*   ei   = (const int*)  d_in[2];
    const float* k1W1 = (const float*)d_in[3];
    const float* k1b1 = (const float*)d_in[4];
    const float* k1W2 = (const float*)d_in[5];
    const float* k1b2 = (const float*)d_in[6];
    const float* k2W1 = (const float*)d_in[7];
    const float* k2b1 = (const float*)d_in[8];
    const float* k2W2 = (const float*)d_in[9];
    const float* k2b2 = (const float*)d_in[10];
    const float* mW   = (const float*)d_in[11];
    const float* mb   = (const float*)d_in[12];
    float* out = (float*)d_out;

    const int n = in_sizes[0] / DIM;       // 100000
    const int e = in_sizes[2] / 2;         // 3200000

    const int node_blocks = (n + 31) / 32;
    const int edge_blocks = (e + 255) / 256;
    const int mix_blocks  = (n + 63) / 64;

    // K1: ky_v = blockmm(x, W_y(ea));  also zeroes acc/cnt
    fused_node_kernel<0><<<node_blocks, 128>>>(x, ea, k1W1, k1b1, k1W2, k1b2, n);
    // scatter-sum + counts
    scatter_kernel<<<edge_blocks, 256>>>(ei, e);
    // K2: v = blockmm(acc/cnt, W_x(ea))  (mean folded into epilogue)
    fused_node_kernel<1><<<node_blocks, 128>>>(nullptr, ea, k2W1, k2b1, k2W2, k2b2, n);
    // mix linear
    mix_kernel<<<mix_blocks, 256>>>(mW, mb, out, n);
}

// round 4
// speedup vs baseline: 2.1685x; 2.1685x over previous
#include <cuda_runtime.h>
#include <cuda_bf16.h>
#include <cstdint>

#define NN   100000
#define TILE 128

// ---- scratch (allocation-free rule: __device__ globals) ----
__device__ float g_kyv[NN * 64];   // K1 output ky_v
__device__ float g_acc[NN * 64];   // scatter accumulator
__device__ float g_cnt[NN];        // scatter counts

// ============================================================================
// helpers
// ============================================================================
__device__ __forceinline__ uint32_t smem_u32(const void* p) {
    uint32_t a;
    asm("{ .reg .u64 t; cvta.to.shared.u64 t, %1; cvt.u32.u64 %0, t; }" : "=r"(a) : "l"(p));
    return a;
}
__device__ __forceinline__ void split_pack(float v0, float v1, uint32_t& hiw, uint32_t& low) {
    __nv_bfloat16 h0 = __float2bfloat16(v0), h1 = __float2bfloat16(v1);
    __nv_bfloat16 l0 = __float2bfloat16(v0 - __bfloat162float(h0));
    __nv_bfloat16 l1 = __float2bfloat16(v1 - __bfloat162float(h1));
    hiw = (uint32_t)__bfloat16_as_ushort(h0) | ((uint32_t)__bfloat16_as_ushort(h1) << 16);
    low = (uint32_t)__bfloat16_as_ushort(l0) | ((uint32_t)__bfloat16_as_ushort(l1) << 16);
}
__device__ __forceinline__ void lda4(uint32_t* r, uint32_t addr) {
    asm volatile("ldmatrix.sync.aligned.m8n8.x4.shared.b16 {%0,%1,%2,%3}, [%4];"
        : "=r"(r[0]), "=r"(r[1]), "=r"(r[2]), "=r"(r[3]) : "r"(addr));
}
__device__ __forceinline__ void ldb2(uint32_t* r, uint32_t addr) {
    asm volatile("ldmatrix.sync.aligned.m8n8.x2.shared.b16 {%0,%1}, [%2];"
        : "=r"(r[0]), "=r"(r[1]) : "r"(addr));
}
__device__ __forceinline__ void mma16816(float* c, const uint32_t* a, const uint32_t* b) {
    asm volatile("mma.sync.aligned.m16n8k16.row.col.f32.bf16.bf16.f32 "
        "{%0,%1,%2,%3}, {%4,%5,%6,%7}, {%8,%9}, {%0,%1,%2,%3};"
        : "+f"(c[0]), "+f"(c[1]), "+f"(c[2]), "+f"(c[3])
        : "r"(a[0]), "r"(a[1]), "r"(a[2]), "r"(a[3]), "r"(b[0]), "r"(b[1]));
}

// smem layout (bytes). A/B rows padded to 144B (16B-aligned rows for ldmatrix;
// 144 mod 128 = 16 -> ldmatrix rows spread across all banks, conflict-free).
// CW rows are 68 floats (272B, 16B-aligned per row).
enum { O_AHI = 0,                       // H hi   : 128 x 144 = 18432
       O_ALO = 18432,                   // H lo   : 128 x 144
       O_BHI = 36864,                   // Bt hi  :  64 x 144 = 9216 (per N-group)
       O_BLO = 46080,                   // Bt lo  :  64 x 144
       O_CW  = 55296,                   // C stage: 128 x 68 f32 = 34816 (also v / mix)
       O_B2  = 90112,                   // b2 chunk: 256 f32
       SMEM_SZ = 91136 };
// mix weight (transposed, stride 68 f32) reuses O_AHI region (64*68*4 = 17408)

// ============================================================================
// Fused node kernel. Phase A: C = H @ W2c^T on HMMA (bf16x3), b2 folded.
// Phase B: y[n,c,j] = sum_k src[n,ck] * C[n,kj].  K1 -> g_kyv (+zero acc/cnt).
// K2: reads g_acc, folds 1/cnt and the mix Linear, writes final out.
// ============================================================================
template<int IS_K2>
__global__ __launch_bounds__(256, 2)
void node_kernel(const float* __restrict__ xin, const float* __restrict__ ea,
                 const float* __restrict__ W1, const float* __restrict__ b1,
                 const float* __restrict__ W2, const float* __restrict__ b2,
                 const float* __restrict__ mW, const float* __restrict__ mb,
                 float* __restrict__ out, int n)
{
    extern __shared__ __align__(16) char sm[];
    const uint32_t smb = smem_u32(sm);
    const int tid = threadIdx.x, wid = tid >> 5, lane = tid & 31;
    const int nb = blockIdx.x * TILE;

    // ---- stage A: h = relu(ea@W1+b1) hi/lo bf16, [node][m], row 144B ----
    {
        const int node = tid >> 1, jh2 = tid & 1;
        const bool ok = (nb + node) < n;
        float e0 = 0.f, e1 = 0.f, e2 = 0.f;
        if (ok) { const float* e = ea + (size_t)(nb + node) * 3; e0 = e[0]; e1 = e[1]; e2 = e[2]; }
        #pragma unroll
        for (int mm = 0; mm < 16; mm++) {
            int m = jh2 * 32 + mm * 2;
            float h0 = 0.f, h1 = 0.f;
            if (ok) {
                h0 = fmaxf(fmaf(e2, W1[128 + m],     fmaf(e1, W1[64 + m],     fmaf(e0, W1[m],     b1[m]))),     0.f);
                h1 = fmaxf(fmaf(e2, W1[128 + m + 1], fmaf(e1, W1[64 + m + 1], fmaf(e0, W1[m + 1], b1[m + 1]))), 0.f);
            }
            uint32_t hiw, low;
            split_pack(h0, h1, hiw, low);
            uint32_t off = (uint32_t)(node * 144 + m * 2);
            *(uint32_t*)(sm + O_AHI + off) = hiw;
            *(uint32_t*)(sm + O_ALO + off) = low;
        }
    }
    // ---- K1: zero scatter accumulators for this tile ----
    if (!IS_K2) {
        const float4 z4 = make_float4(0.f, 0.f, 0.f, 0.f);
        #pragma unroll
        for (int i = 0; i < 8; i++) {
            int idx4 = tid + i * 256;               // 2048 float4 per tile
            int node = idx4 >> 4;
            if (nb + node < n) ((float4*)g_acc)[(size_t)nb * 16 + idx4] = z4;
        }
        if (tid < TILE && nb + tid < n) g_cnt[nb + tid] = 0.f;
    }

    const int node_b = tid >> 1, jh = tid & 1;     // phase-B: node + j-half
    const bool validb = (nb + node_b) < n;
    const float* src = IS_K2 ? g_acc : xin;
    float inv = 1.0f;
    if (IS_K2 && validb) inv = 1.0f / fmaxf(g_cnt[nb + node_b], 1.0f);

    // per-lane ldmatrix address components (pitch 144 = 16B-aligned rows)
    const uint32_t aRow = (uint32_t)((wid * 16 + (lane & 15)) * 144 + ((lane >> 4) * 16));
    const uint32_t bRow = (uint32_t)((lane & 7) * 144 + (((lane >> 3) & 1) * 16));
    const int r0   = wid * 16 + (lane >> 2);       // C frag row
    const int colq = 2 * (lane & 3);               // C frag col pair

    float vfull[IS_K2 ? 32 : 1];

    __syncthreads();

    for (int c = 0; c < 4; c++) {
        if (tid < 64) ((float4*)(sm + O_B2))[tid] = ((const float4*)(b2 + c * 256))[tid];
        float y[8] = {0.f, 0.f, 0.f, 0.f, 0.f, 0.f, 0.f, 0.f};

        for (int g = 0; g < 4; g++) {
            __syncthreads();                       // CW consumed; sb2 visible (g=0)
            // ---- stage Bt[col][m] hi/lo for this N=64 group ----
            #pragma unroll
            for (int it = 0; it < 8; it++) {
                int p = tid + it * 256;            // 2048 (col,m-pair)
                int col = p & 63, m2 = p >> 6;
                float w0 = W2[(size_t)(2 * m2)     * 1024 + c * 256 + g * 64 + col];
                float w1 = W2[(size_t)(2 * m2 + 1) * 1024 + c * 256 + g * 64 + col];
                uint32_t hiw, low;
                split_pack(w0, w1, hiw, low);
                uint32_t off = (uint32_t)(col * 144 + m2 * 4);
                *(uint32_t*)(sm + O_BHI + off) = hiw;
                *(uint32_t*)(sm + O_BLO + off) = low;
            }
            __syncthreads();                       // B ready

            // ---- HMMA: acc = Ah*Bh + Ah*Bl + Al*Bh over K=64 ----
            float acc[8][4];
            #pragma unroll
            for (int ct = 0; ct < 8; ct++)
                #pragma unroll
                for (int q = 0; q < 4; q++) acc[ct][q] = 0.f;
            #pragma unroll
            for (int pass = 0; pass < 3; pass++) {
                const uint32_t Ab = smb + ((pass < 2) ? O_AHI : O_ALO);
                const uint32_t Bb = smb + ((pass == 1) ? O_BLO : O_BHI);
                #pragma unroll
                for (int ks = 0; ks < 4; ks++) {
                    uint32_t a[4];
                    lda4(a, Ab + aRow + ks * 32);
                    #pragma unroll
                    for (int ct = 0; ct < 8; ct++) {
                        uint32_t b[2];
                        ldb2(b, Bb + (uint32_t)(ct * 1152) + bRow + ks * 32);
                        mma16816(acc[ct], a, b);
                    }
                }
            }
            // ---- stage C (+b2) into CW [128][68] ----
            #pragma unroll
            for (int ct = 0; ct < 8; ct++) {
                int cl = ct * 8 + colq;
                float2 bb = *(const float2*)(sm + O_B2 + (g * 64 + cl) * 4);
                *(float2*)(sm + O_CW + (r0 * 68 + cl) * 4) =
                    make_float2(acc[ct][0] + bb.x, acc[ct][1] + bb.y);
                *(float2*)(sm + O_CW + ((r0 + 8) * 68 + cl) * 4) =
                    make_float2(acc[ct][2] + bb.x, acc[ct][3] + bb.y);
            }
            __syncthreads();                       // CW ready

            // ---- phase B partial: k = g*4 .. g*4+3 ----
            float4 xk4 = (validb) ? *(const float4*)&src[(size_t)(nb + node_b) * 64 + c * 16 + g * 4]
                                  : make_float4(0.f, 0.f, 0.f, 0.f);
            float xk[4] = {xk4.x, xk4.y, xk4.z, xk4.w};
            #pragma unroll
            for (int kl = 0; kl < 4; kl++) {
                const char* base = sm + O_CW + (node_b * 68 + kl * 16 + jh * 8) * 4;
                float4 w0 = *(const float4*)base;
                float4 w1 = *(const float4*)(base + 16);
                y[0] = fmaf(xk[kl], w0.x, y[0]); y[1] = fmaf(xk[kl], w0.y, y[1]);
                y[2] = fmaf(xk[kl], w0.z, y[2]); y[3] = fmaf(xk[kl], w0.w, y[3]);
                y[4] = fmaf(xk[kl], w1.x, y[4]); y[5] = fmaf(xk[kl], w1.y, y[5]);
                y[6] = fmaf(xk[kl], w1.z, y[6]); y[7] = fmaf(xk[kl], w1.w, y[7]);
            }
        }
        if (!IS_K2) {
            if (validb) {
                float* dst = &g_kyv[(size_t)(nb + node_b) * 64 + c * 16 + jh * 8];
                *(float4*)dst       = make_float4(y[0], y[1], y[2], y[3]);
                *(float4*)(dst + 4) = make_float4(y[4], y[5], y[6], y[7]);
            }
        } else {
            #pragma unroll
            for (int jj = 0; jj < 8; jj++) vfull[c * 8 + jj] = y[jj] * inv;
        }
    }

    // ---- K2 tail: out = v @ mW^T + mb (v staged in CW, mW^T in O_AHI) ----
    if (IS_K2) {
        __syncthreads();                           // all phase-B reads of CW done
        #pragma unroll
        for (int cc = 0; cc < 4; cc++) {
            char* base = sm + O_CW + (node_b * 68 + cc * 16 + jh * 8) * 4;
            *(float4*)base        = make_float4(vfull[cc*8+0], vfull[cc*8+1], vfull[cc*8+2], vfull[cc*8+3]);
            *(float4*)(base + 16) = make_float4(vfull[cc*8+4], vfull[cc*8+5], vfull[cc*8+6], vfull[cc*8+7]);
        }
        #pragma unroll
        for (int it = 0; it < 16; it++) {
            int p = tid + it * 256;                // 4096
            int j = p >> 6, i = p & 63;
            *(float*)(sm + O_AHI + (j * 68 + i) * 4) = mW[(size_t)i * 64 + j];
        }
        __syncthreads();
        if (validb) {
            float a[32];
            #pragma unroll
            for (int q = 0; q < 8; q++) {
                float4 m4 = ((const float4*)mb)[jh * 8 + q];
                a[q*4] = m4.x; a[q*4+1] = m4.y; a[q*4+2] = m4.z; a[q*4+3] = m4.w;
            }
            #pragma unroll 4
            for (int j = 0; j < 64; j++) {
                float vj = *(const float*)(sm + O_CW + (node_b * 68 + j) * 4);
                #pragma unroll
                for (int q = 0; q < 8; q++) {
                    float4 w = *(const float4*)(sm + O_AHI + (j * 68 + jh * 32 + q * 4) * 4);
                    a[q*4]   = fmaf(vj, w.x, a[q*4]);
                    a[q*4+1] = fmaf(vj, w.y, a[q*4+1]);
                    a[q*4+2] = fmaf(vj, w.z, a[q*4+2]);
                    a[q*4+3] = fmaf(vj, w.w, a[q*4+3]);
                }
            }
            float* dst = &out[(size_t)(nb + node_b) * 64 + jh * 32];
            #pragma unroll
            for (int q = 0; q < 8; q++)
                ((float4*)dst)[q] = make_float4(a[q*4], a[q*4+1], a[q*4+2], a[q*4+3]);
        }
    }
}

// ============================================================================
// Edge scatter: acc[dst] += ky_v[src], cnt[dst] += 1.  float4 vector atomics.
// ============================================================================
__global__ __launch_bounds__(256)
void scatter_kernel(const int* __restrict__ ei, int n_edges)
{
    __shared__ int s_dst[256];
    __shared__ int s_src[256];
    const int tid  = threadIdx.x;
    const int base = blockIdx.x * 256;
    const int nE   = min(256, n_edges - base);
    if (nE <= 0) return;

    if (tid < nE) {
        s_dst[tid] = ei[base + tid];
        s_src[tid] = ei[n_edges + base + tid];
    }
    __syncthreads();

    const int w    = tid >> 5;
    const int lane = tid & 31;
    const int half16 = lane >> 4;
    const int l16  = lane & 15;

    #pragma unroll 4
    for (int p = 0; p < 16; p++) {
        int le = w * 32 + p * 2 + half16;
        if (le < nE) {
            int src = s_src[le];
            int dst = s_dst[le];
            float4 v = *(const float4*)&g_kyv[(size_t)src * 64 + l16 * 4];
            atomicAdd((float4*)&g_acc[(size_t)dst * 64 + l16 * 4], v);
            if (l16 == 0) atomicAdd(&g_cnt[dst], 1.0f);
        }
    }
}

// ============================================================================
extern "C" void kernel_launch(void* const* d_in, const int* in_sizes, int n_in,
                              void* d_out, int out_size)
{
    const float* x    = (const float*)d_in[0];
    const float* ea   = (const float*)d_in[1];
    const int*   ei   = (const int*)  d_in[2];
    const float* k1W1 = (const float*)d_in[3];
    const float* k1b1 = (const float*)d_in[4];
    const float* k1W2 = (const float*)d_in[5];
    const float* k1b2 = (const float*)d_in[6];
    const float* k2W1 = (const float*)d_in[7];
    const float* k2b1 = (const float*)d_in[8];
    const float* k2W2 = (const float*)d_in[9];
    const float* k2b2 = (const float*)d_in[10];
    const float* mW   = (const float*)d_in[11];
    const float* mb   = (const float*)d_in[12];
    float* out = (float*)d_out;

    const int n = in_sizes[0] / 64;        // 100000
    const int e = in_sizes[2] / 2;         // 3200000

    cudaFuncSetAttribute(node_kernel<0>, cudaFuncAttributeMaxDynamicSharedMemorySize, SMEM_SZ);
    cudaFuncSetAttribute(node_kernel<1>, cudaFuncAttributeMaxDynamicSharedMemorySize, SMEM_SZ);

    const int node_blocks = (n + TILE - 1) / TILE;
    const int edge_blocks = (e + 255) / 256;

    node_kernel<0><<<node_blocks, 256, SMEM_SZ>>>(x, ea, k1W1, k1b1, k1W2, k1b2,
                                                  nullptr, nullptr, nullptr, n);
    scatter_kernel<<<edge_blocks, 256>>>(ei, e);
    node_kernel<1><<<node_blocks, 256, SMEM_SZ>>>(nullptr, ea, k2W1, k2b1, k2W2, k2b2,
                                                  mW, mb, out, n);
}

// round 6
// speedup vs baseline: 3.1126x; 1.4353x over previous
#include <cuda_runtime.h>
#include <cuda_bf16.h>
#include <cstdint>

#define NN   100000
#define TILE 128

// ---- scratch (allocation-free rule: __device__ globals) ----
__device__ float g_kyv[NN * 64];            // K1 output ky_v
__device__ float g_acc[NN * 64];            // scatter accumulator
__device__ float g_cnt[NN];                 // scatter counts
__device__ uint32_t g_Bhi[2][16][2048];     // prepacked W2 hi bf16 pairs [kid][c*4+g][col*32+m2]
__device__ uint32_t g_Blo[2][16][2048];     // prepacked W2 lo

// ============================================================================
// helpers
// ============================================================================
__device__ __forceinline__ uint32_t smem_u32(const void* p) {
    uint32_t a;
    asm("{ .reg .u64 t; cvta.to.shared.u64 t, %1; cvt.u32.u64 %0, t; }" : "=r"(a) : "l"(p));
    return a;
}
__device__ __forceinline__ void split_pack(float v0, float v1, uint32_t& hiw, uint32_t& low) {
    __nv_bfloat16 h0 = __float2bfloat16(v0), h1 = __float2bfloat16(v1);
    __nv_bfloat16 l0 = __float2bfloat16(v0 - __bfloat162float(h0));
    __nv_bfloat16 l1 = __float2bfloat16(v1 - __bfloat162float(h1));
    hiw = (uint32_t)__bfloat16_as_ushort(h0) | ((uint32_t)__bfloat16_as_ushort(h1) << 16);
    low = (uint32_t)__bfloat16_as_ushort(l0) | ((uint32_t)__bfloat16_as_ushort(l1) << 16);
}
__device__ __forceinline__ void lda4(uint32_t* r, uint32_t addr) {
    asm volatile("ldmatrix.sync.aligned.m8n8.x4.shared.b16 {%0,%1,%2,%3}, [%4];"
        : "=r"(r[0]), "=r"(r[1]), "=r"(r[2]), "=r"(r[3]) : "r"(addr));
}
__device__ __forceinline__ void ldb2(uint32_t* r, uint32_t addr) {
    asm volatile("ldmatrix.sync.aligned.m8n8.x2.shared.b16 {%0,%1}, [%2];"
        : "=r"(r[0]), "=r"(r[1]) : "r"(addr));
}
__device__ __forceinline__ void mma16816(float* c, const uint32_t* a, const uint32_t* b) {
    asm volatile("mma.sync.aligned.m16n8k16.row.col.f32.bf16.bf16.f32 "
        "{%0,%1,%2,%3}, {%4,%5,%6,%7}, {%8,%9}, {%0,%1,%2,%3};"
        : "+f"(c[0]), "+f"(c[1]), "+f"(c[2]), "+f"(c[3])
        : "r"(a[0]), "r"(a[1]), "r"(a[2]), "r"(a[3]), "r"(b[0]), "r"(b[1]));
}

// smem layout (bytes). A/B rows 144B (16B-aligned rows for ldmatrix; 144 mod 128
// = 16 -> conflict-free). K2 tail reuses [0..34816) for v (pitch 68 f32) and
// [O_BHI..) for mW^T (pitch 68 f32, 17408B).
enum { O_AHI = 0,                       // H hi : 128 x 144 = 18432
       O_ALO = 18432,                   // H lo : 128 x 144
       O_BHI = 36864,                   // Bt hi:  64 x 144 = 9216
       O_BLO = 46080,                   // Bt lo:  64 x 144
       O_B2  = 55296,                   // b2 chunk: 256 f32
       SMEM_SZ = 56320 };

// ============================================================================
// prep: W2 -> bf16 hi/lo, ldmatrix tile layout [col][m2]. 32 blocks, ~5us.
// ============================================================================
__global__ __launch_bounds__(256)
void prep_kernel(const float* __restrict__ W2a, const float* __restrict__ W2b)
{
    const int b = blockIdx.x;              // 0..31
    const int k = b >> 4, t = b & 15;
    const int c = t >> 2, g = t & 3;
    const float* W2 = k ? W2b : W2a;
    const int tid = threadIdx.x;
    #pragma unroll
    for (int it = 0; it < 8; it++) {
        int p = tid + it * 256;            // 2048
        int col = p & 63, m2 = p >> 6;
        float w0 = W2[(size_t)(2 * m2)     * 1024 + c * 256 + g * 64 + col];
        float w1 = W2[(size_t)(2 * m2 + 1) * 1024 + c * 256 + g * 64 + col];
        uint32_t hi, lo;
        split_pack(w0, w1, hi, lo);
        g_Bhi[k][t][col * 32 + m2] = hi;
        g_Blo[k][t][col * 32 + m2] = lo;
    }
}

// ============================================================================
// Fused node kernel. Phase A: C = H @ W2c^T on HMMA (bf16x3, Bh/Ah frags
// register-cached). Phase B: fully register-resident per-lane contraction.
// K1 -> g_kyv (+zero acc/cnt).  K2: reads g_acc, folds 1/cnt + mix Linear.
// ============================================================================
template<int IS_K2>
__global__ __launch_bounds__(256, IS_K2 ? 2 : 3)
void node_kernel(const float* __restrict__ xin, const float* __restrict__ ea,
                 const float* __restrict__ W1, const float* __restrict__ b1,
                 const float* __restrict__ b2,
                 const float* __restrict__ mW, const float* __restrict__ mb,
                 float* __restrict__ out, int n)
{
    extern __shared__ __align__(16) char sm[];
    const uint32_t smb = smem_u32(sm);
    const int tid = threadIdx.x, wid = tid >> 5, lane = tid & 31;
    const int nb = blockIdx.x * TILE;

    // ---- stage A: h = relu(ea@W1+b1) hi/lo bf16, [node][m], row 144B ----
    {
        const int node = tid >> 1, mh = tid & 1;
        const bool ok = (nb + node) < n;
        float e0 = 0.f, e1 = 0.f, e2 = 0.f;
        if (ok) { const float* e = ea + (size_t)(nb + node) * 3; e0 = e[0]; e1 = e[1]; e2 = e[2]; }
        #pragma unroll
        for (int mm = 0; mm < 16; mm++) {
            int m = mh * 32 + mm * 2;
            float h0 = 0.f, h1 = 0.f;
            if (ok) {
                h0 = fmaxf(fmaf(e2, W1[128 + m],     fmaf(e1, W1[64 + m],     fmaf(e0, W1[m],     b1[m]))),     0.f);
                h1 = fmaxf(fmaf(e2, W1[128 + m + 1], fmaf(e1, W1[64 + m + 1], fmaf(e0, W1[m + 1], b1[m + 1]))), 0.f);
            }
            uint32_t hiw, low;
            split_pack(h0, h1, hiw, low);
            uint32_t off = (uint32_t)(node * 144 + m * 2);
            *(uint32_t*)(sm + O_AHI + off) = hiw;
            *(uint32_t*)(sm + O_ALO + off) = low;
        }
    }
    // ---- K1: zero scatter accumulators for this tile ----
    if (!IS_K2) {
        const float4 z4 = make_float4(0.f, 0.f, 0.f, 0.f);
        #pragma unroll
        for (int i = 0; i < 8; i++) {
            int idx4 = tid + i * 256;
            int node = idx4 >> 4;
            if (nb + node < n) ((float4*)g_acc)[(size_t)nb * 16 + idx4] = z4;
        }
        if (tid < TILE && nb + tid < n) g_cnt[nb + tid] = 0.f;
    }

    // per-lane ldmatrix address components (pitch 144)
    const uint32_t aRow = (uint32_t)((wid * 16 + (lane & 15)) * 144 + ((lane >> 4) * 16));
    const uint32_t bRow = (uint32_t)((lane & 7) * 144 + (((lane >> 3) & 1) * 16));
    const int r0   = wid * 16 + (lane >> 2);       // C frag rows r0, r0+8
    const int colq = 2 * (lane & 3);

    const int row0 = nb + r0, row1 = nb + r0 + 8;
    const bool v0 = row0 < n, v1 = row1 < n;
    const float* src = IS_K2 ? g_acc : xin;
    float inv0 = 1.f, inv1 = 1.f;
    if (IS_K2) {
        if (v0) inv0 = 1.0f / fmaxf(g_cnt[row0], 1.0f);
        if (v1) inv1 = 1.0f / fmaxf(g_cnt[row1], 1.0f);
    }

    float vfull[IS_K2 ? 32 : 1];

    for (int c = 0; c < 4; c++) {
        float y[8] = {0.f, 0.f, 0.f, 0.f, 0.f, 0.f, 0.f, 0.f};

        for (int gg = 0; gg < 4; gg++) {
            __syncthreads();                       // prior MMA/phase-B reads done
            if (gg == 0 && tid < 64)
                ((float4*)(sm + O_B2))[tid] = ((const float4*)(b2 + c * 256))[tid];
            // ---- stage prepacked B tile (hi+lo): 512 uint4 each ----
            {
                const uint32_t* bhT = g_Bhi[IS_K2][c * 4 + gg];
                const uint32_t* blT = g_Blo[IS_K2][c * 4 + gg];
                #pragma unroll
                for (int it = 0; it < 2; it++) {
                    int p = tid + it * 256;        // 512
                    int col = p >> 3, m2s = (p & 7) * 4;
                    uint4 vh = ((const uint4*)bhT)[p];
                    uint4 vl = ((const uint4*)blT)[p];
                    *(uint4*)(sm + O_BHI + col * 144 + m2s * 4) = vh;
                    *(uint4*)(sm + O_BLO + col * 144 + m2s * 4) = vl;
                }
            }
            __syncthreads();                       // B + b2 ready

            // ---- HMMA: acc = Ah*Bh + Ah*Bl + Al*Bh (Bh/Ah frags cached) ----
            float acc[8][4];
            #pragma unroll
            for (int ct = 0; ct < 8; ct++)
                #pragma unroll
                for (int q = 0; q < 4; q++) acc[ct][q] = 0.f;
            #pragma unroll
            for (int ks = 0; ks < 4; ks++) {
                uint32_t ah[4], al[4], bh[8][2];
                lda4(ah, smb + O_AHI + aRow + ks * 32);
                #pragma unroll
                for (int ct = 0; ct < 8; ct++) {
                    ldb2(bh[ct], smb + O_BHI + (uint32_t)(ct * 1152) + bRow + ks * 32);
                    mma16816(acc[ct], ah, bh[ct]);
                }
                #pragma unroll
                for (int ct = 0; ct < 8; ct++) {
                    uint32_t bl[2];
                    ldb2(bl, smb + O_BLO + (uint32_t)(ct * 1152) + bRow + ks * 32);
                    mma16816(acc[ct], ah, bl);
                }
                lda4(al, smb + O_ALO + aRow + ks * 32);
                #pragma unroll
                for (int ct = 0; ct < 8; ct++)
                    mma16816(acc[ct], al, bh[ct]);
            }

            // ---- phase B (registers): k_local = ct>>1, j = (ct&1)*8+colq+q ----
            float4 x0 = make_float4(0.f, 0.f, 0.f, 0.f), x1 = x0;
            if (v0) x0 = *(const float4*)&src[(size_t)row0 * 64 + c * 16 + gg * 4];
            if (v1) x1 = *(const float4*)&src[(size_t)row1 * 64 + c * 16 + gg * 4];
            float xk0[4] = {x0.x, x0.y, x0.z, x0.w};
            float xk1[4] = {x1.x, x1.y, x1.z, x1.w};
            const float* b2s = (const float*)(sm + O_B2);
            #pragma unroll
            for (int ct = 0; ct < 8; ct++) {
                float2 bb = *(const float2*)&b2s[gg * 64 + ct * 8 + colq];
                int kl = ct >> 1, jb = (ct & 1) * 2;
                y[jb]     = fmaf(xk0[kl], acc[ct][0] + bb.x, y[jb]);
                y[jb + 1] = fmaf(xk0[kl], acc[ct][1] + bb.y, y[jb + 1]);
                y[4 + jb]     = fmaf(xk1[kl], acc[ct][2] + bb.x, y[4 + jb]);
                y[4 + jb + 1] = fmaf(xk1[kl], acc[ct][3] + bb.y, y[4 + jb + 1]);
            }
        }

        if (!IS_K2) {
            if (v0) {
                *(float2*)&g_kyv[(size_t)row0 * 64 + c * 16 + colq]     = make_float2(y[0], y[1]);
                *(float2*)&g_kyv[(size_t)row0 * 64 + c * 16 + 8 + colq] = make_float2(y[2], y[3]);
            }
            if (v1) {
                *(float2*)&g_kyv[(size_t)row1 * 64 + c * 16 + colq]     = make_float2(y[4], y[5]);
                *(float2*)&g_kyv[(size_t)row1 * 64 + c * 16 + 8 + colq] = make_float2(y[6], y[7]);
            }
        } else {
            #pragma unroll
            for (int s = 0; s < 4; s++) vfull[c * 8 + s] = y[s] * inv0;
            #pragma unroll
            for (int s = 4; s < 8; s++) vfull[c * 8 + s] = y[s] * inv1;
        }
    }

    // ---- K2 tail: out = v @ mW^T + mb.  v -> smem pitch 68 (reuses A region);
    //      mW^T -> O_BHI pitch 68.
    if (IS_K2) {
        __syncthreads();                           // all MMA reads of A done
        #pragma unroll
        for (int c = 0; c < 4; c++) {
            *(float2*)(sm + r0 * 272 + (c * 16 + colq) * 4)           = make_float2(vfull[c*8+0], vfull[c*8+1]);
            *(float2*)(sm + r0 * 272 + (c * 16 + 8 + colq) * 4)       = make_float2(vfull[c*8+2], vfull[c*8+3]);
            *(float2*)(sm + (r0 + 8) * 272 + (c * 16 + colq) * 4)     = make_float2(vfull[c*8+4], vfull[c*8+5]);
            *(float2*)(sm + (r0 + 8) * 272 + (c * 16 + 8 + colq) * 4) = make_float2(vfull[c*8+6], vfull[c*8+7]);
        }
        #pragma unroll
        for (int it = 0; it < 16; it++) {
            int p = tid + it * 256;                // 4096
            int j = p >> 6, i = p & 63;
            *(float*)(sm + O_BHI + (j * 68 + i) * 4) = mW[(size_t)i * 64 + j];
        }
        __syncthreads();
        const int node_b = tid >> 1, jh = tid & 1;
        if (nb + node_b < n) {
            float a[32];
            #pragma unroll
            for (int q = 0; q < 8; q++) {
                float4 m4 = ((const float4*)mb)[jh * 8 + q];
                a[q*4] = m4.x; a[q*4+1] = m4.y; a[q*4+2] = m4.z; a[q*4+3] = m4.w;
            }
            #pragma unroll 4
            for (int j = 0; j < 64; j++) {
                float vj = *(const float*)(sm + (node_b * 68 + j) * 4);
                #pragma unroll
                for (int q = 0; q < 8; q++) {
                    float4 w = *(const float4*)(sm + O_BHI + (j * 68 + jh * 32 + q * 4) * 4);
                    a[q*4]   = fmaf(vj, w.x, a[q*4]);
                    a[q*4+1] = fmaf(vj, w.y, a[q*4+1]);
                    a[q*4+2] = fmaf(vj, w.z, a[q*4+2]);
                    a[q*4+3] = fmaf(vj, w.w, a[q*4+3]);
                }
            }
            float* dst = &out[(size_t)(nb + node_b) * 64 + jh * 32];
            #pragma unroll
            for (int q = 0; q < 8; q++)
                ((float4*)dst)[q] = make_float4(a[q*4], a[q*4+1], a[q*4+2], a[q*4+3]);
        }
    }
}

// ============================================================================
// Edge scatter: acc[dst] += ky_v[src], cnt[dst] += 1.  float4 vector atomics.
// ============================================================================
__global__ __launch_bounds__(256)
void scatter_kernel(const int* __restrict__ ei, int n_edges)
{
    __shared__ int s_dst[256];
    __shared__ int s_src[256];
    const int tid  = threadIdx.x;
    const int base = blockIdx.x * 256;
    const int nE   = min(256, n_edges - base);
    if (nE <= 0) return;

    if (tid < nE) {
        s_dst[tid] = ei[base + tid];
        s_src[tid] = ei[n_edges + base + tid];
    }
    __syncthreads();

    const int w = tid >> 5, lane = tid & 31;
    const int half16 = lane >> 4, l16 = lane & 15;

    #pragma unroll 4
    for (int p = 0; p < 16; p++) {
        int le = w * 32 + p * 2 + half16;
        if (le < nE) {
            int src = s_src[le];
            int dst = s_dst[le];
            float4 v = *(const float4*)&g_kyv[(size_t)src * 64 + l16 * 4];
            atomicAdd((float4*)&g_acc[(size_t)dst * 64 + l16 * 4], v);
            if (l16 == 0) atomicAdd(&g_cnt[dst], 1.0f);
        }
    }
}

// ============================================================================
extern "C" void kernel_launch(void* const* d_in, const int* in_sizes, int n_in,
                              void* d_out, int out_size)
{
    const float* x    = (const float*)d_in[0];
    const float* ea   = (const float*)d_in[1];
    const int*   ei   = (const int*)  d_in[2];
    const float* k1W1 = (const float*)d_in[3];
    const float* k1b1 = (const float*)d_in[4];
    const float* k1W2 = (const float*)d_in[5];
    const float* k1b2 = (const float*)d_in[6];
    const float* k2W1 = (const float*)d_in[7];
    const float* k2b1 = (const float*)d_in[8];
    const float* k2W2 = (const float*)d_in[9];
    const float* k2b2 = (const float*)d_in[10];
    const float* mW   = (const float*)d_in[11];
    const float* mb   = (const float*)d_in[12];
    float* out = (float*)d_out;

    const int n = in_sizes[0] / 64;        // 100000
    const int e = in_sizes[2] / 2;         // 3200000

    cudaFuncSetAttribute(node_kernel<0>, cudaFuncAttributeMaxDynamicSharedMemorySize, SMEM_SZ);
    cudaFuncSetAttribute(node_kernel<1>, cudaFuncAttributeMaxDynamicSharedMemorySize, SMEM_SZ);

    const int node_blocks = (n + TILE - 1) / TILE;
    const int edge_blocks = (e + 255) / 256;

    prep_kernel<<<32, 256>>>(k1W2, k2W2);
    node_kernel<0><<<node_blocks, 256, SMEM_SZ>>>(x, ea, k1W1, k1b1, k1b2,
                                                  nullptr, nullptr, nullptr, n);
    scatter_kernel<<<edge_blocks, 256>>>(ei, e);
    node_kernel<1><<<node_blocks, 256, SMEM_SZ>>>(nullptr, ea, k2W1, k2b1, k2b2,
                                                  mW, mb, out, n);
}